// round 17
// baseline (speedup 1.0000x reference)
#include <cuda_runtime.h>

#define DIM      4096
#define B        8
#define KV_DIM   1024   // N_KV_HEADS * HEAD_DIM
#define TOTAL    16384

// Scratch (allocation-free rule: __device__ globals)
// Two partial up-proj results (k-split halves); down_proj sums them.
__device__ __align__(16) float g_xp[2][B * KV_DIM];
__device__ __align__(16) float g_y[B * DIM];     // down-proj result [b][o]

__device__ __forceinline__ float dot4(float4 a, float4 b) {
    return a.x * b.x + a.y * b.y + a.z * b.z + a.w * b.w;
}

// ---------------------------------------------------------------------------
// Kernel 1: partial x[b][r] = sum over HALF of k of emb[b][k] * Wup[r][k]
// grid = 1024: blockIdx = (row-pair 0..511) x (k-half 0..1).
// Per thread: 4 W DRAM loads + 16 L1-hot emb loads + 32 dot4 — half the
// serial chain of the R13 config, double the block count.
// ---------------------------------------------------------------------------
__global__ void __launch_bounds__(256) up_proj_kernel(
    const float* __restrict__ emb, const float* __restrict__ Wup)
{
    const int tid  = threadIdx.x;
    const int lane = tid & 31;
    const int wid  = tid >> 5;              // 0..7
    const int r0   = (blockIdx.x >> 1) * 2; // rows r0, r0+1
    const int half = blockIdx.x & 1;        // k-half
    const float4* w4 = reinterpret_cast<const float4*>(Wup);
    const float4* e4 = reinterpret_cast<const float4*>(emb);

    float acc[2][B];
#pragma unroll
    for (int i = 0; i < 2; i++)
#pragma unroll
        for (int b = 0; b < B; b++) acc[i][b] = 0.f;

#pragma unroll
    for (int s = 0; s < 2; s++) {
        const int q = half * 512 + wid * 64 + s * 32 + lane;  // float4 idx
        const float4 w0 = __ldg(&w4[(size_t)r0 * 1024 + q]);
        const float4 w1 = __ldg(&w4[(size_t)(r0 + 1) * 1024 + q]);
#pragma unroll
        for (int b = 0; b < B; b++) {
            const float4 e = __ldg(&e4[(size_t)b * 1024 + q]);
            acc[0][b] += dot4(w0, e);
            acc[1][b] += dot4(w1, e);
        }
    }

    __shared__ float s_part[8][2][B];   // [warp][row][b]
#pragma unroll
    for (int i = 0; i < 2; i++)
#pragma unroll
        for (int b = 0; b < B; b++) {
            float v = acc[i][b];
#pragma unroll
            for (int off = 16; off; off >>= 1) v += __shfl_down_sync(0xffffffffu, v, off);
            if (lane == 0) s_part[wid][i][b] = v;
        }
    __syncthreads();
    if (tid < 16) {
        const int row = tid >> 3, b = tid & 7;
        float v = 0.f;
#pragma unroll
        for (int w8 = 0; w8 < 8; w8++) v += s_part[w8][row][b];
        g_xp[half][b * KV_DIM + r0 + row] = v;
    }
}

// ---------------------------------------------------------------------------
// Kernel 2: y[b][o] = sum_j val[b][j] * Wdown[o][j]
//   val[b][j] = x[b][((j>>9)<<7)|(j&127)]  (repeat-interleave remap).
// ALGEBRAIC FOLD: the four W chunks at q = 128c + t + 32u (u=0..3) multiply
// the SAME x float4, so sum them first (12 FADD), then ONE dot4 per batch.
// x is reconstructed as g_xp[0] + g_xp[1] (both L1-resident, 64 KB total).
// ONE row per 256-thread block, grid = 4096. Wdown (64 MB) read once.
// ---------------------------------------------------------------------------
__global__ void __launch_bounds__(256) down_proj_kernel(
    const float* __restrict__ Wdown)
{
    const int tid  = threadIdx.x;
    const int lane = tid & 31;          // t
    const int wid  = tid >> 5;          // c : 512-float j-chunk
    const int o    = blockIdx.x;        // row 0..4095
    const float4* w4 = reinterpret_cast<const float4*>(Wdown + (size_t)o * DIM);

    // 4 independent DRAM loads, front-batched.
    float4 w[4];
#pragma unroll
    for (int u = 0; u < 4; u++) w[u] = __ldg(&w4[wid * 128 + lane + 32 * u]);

    // Fold the repeat group.
    float4 ws;
    ws.x = (w[0].x + w[1].x) + (w[2].x + w[3].x);
    ws.y = (w[0].y + w[1].y) + (w[2].y + w[3].y);
    ws.z = (w[0].z + w[1].z) + (w[2].z + w[3].z);
    ws.w = (w[0].w + w[1].w) + (w[2].w + w[3].w);

    const int xi = wid * 32 + lane;     // shared x float4 index
    const float4* x0 = reinterpret_cast<const float4*>(g_xp[0]);
    const float4* x1 = reinterpret_cast<const float4*>(g_xp[1]);

    float acc[B];
#pragma unroll
    for (int b = 0; b < B; b++) {
        const float4 a = x0[b * 256 + xi];
        const float4 c = x1[b * 256 + xi];
        float4 xv; xv.x = a.x + c.x; xv.y = a.y + c.y;
                   xv.z = a.z + c.z; xv.w = a.w + c.w;
        acc[b] = dot4(ws, xv);
    }

    __shared__ float s_part[8][B];      // [warp][b]
#pragma unroll
    for (int b = 0; b < B; b++) {
        float v = acc[b];
#pragma unroll
        for (int off = 16; off; off >>= 1) v += __shfl_down_sync(0xffffffffu, v, off);
        if (lane == 0) s_part[wid][b] = v;
    }
    __syncthreads();
    if (tid < B) {                      // tid = b
        float v = 0.f;
#pragma unroll
        for (int w8 = 0; w8 < 8; w8++) v += s_part[w8][tid];
        g_y[tid * DIM + o] = v;
    }
}

// ---------------------------------------------------------------------------
// Kernel 3: out[t][:] = y[batch(t)][:]  — 256 MB, HBM-write-bound (floor).
// One token per 128-thread half-block: 128 threads x 8 float4 = exactly one
// full 16 KB row, contiguous streaming stores. y (128 KB) is L1-resident.
// grid = 8192 blocks x 256 threads (2 tokens per block).
// ---------------------------------------------------------------------------
__global__ void __launch_bounds__(256) broadcast_kernel(
    const int* __restrict__ seqlen_raw, float* __restrict__ out)
{
    __shared__ int s_off[B + 1];
    if (threadIdx.x == 0) {
        int sum32 = 0;
#pragma unroll
        for (int i = 0; i < B; i++) sum32 += seqlen_raw[i];
        const bool is64 = (sum32 != TOTAL);   // int64: low word at 2*i (LE)
        int acc = 0;
#pragma unroll
        for (int i = 0; i < B; i++) {
            s_off[i] = acc;
            acc += is64 ? seqlen_raw[2 * i] : seqlen_raw[i];
        }
        s_off[B] = acc;
    }
    __syncthreads();

    const int sub   = threadIdx.x & 127;                      // 0..127
    const int token = blockIdx.x * 2 + (threadIdx.x >> 7);    // one token per half-block

    int b = 0;
#pragma unroll
    for (int i = 1; i < B; i++) b += (token >= s_off[i]);

    const float4* y4 = reinterpret_cast<const float4*>(&g_y[b * DIM]);
    float4* o4 = reinterpret_cast<float4*>(out) + (size_t)token * 1024;

    float4 v[8];
#pragma unroll
    for (int k = 0; k < 8; k++) v[k] = __ldg(&y4[sub + k * 128]);
#pragma unroll
    for (int k = 0; k < 8; k++) __stcs(&o4[sub + k * 128], v[k]);
}

// ---------------------------------------------------------------------------
// Inputs (metadata order): embedding [8,4096] f32, W_up [1024,4096] f32,
// W_down [4096,4096] f32, seqlen [8] int. Output: [16384,4096] f32.
// ---------------------------------------------------------------------------
extern "C" void kernel_launch(void* const* d_in, const int* in_sizes, int n_in,
                              void* d_out, int out_size)
{
    const float* emb    = (const float*)d_in[0];
    const float* Wup    = (const float*)d_in[1];
    const float* Wdown  = (const float*)d_in[2];
    const int*   seqlen = (const int*)d_in[3];
    float* out = (float*)d_out;

    up_proj_kernel<<<KV_DIM, 256>>>(emb, Wup);     // 512 row-pairs x 2 k-halves
    down_proj_kernel<<<DIM, 256>>>(Wdown);
    broadcast_kernel<<<TOTAL / 2, 256>>>(seqlen, out);
}